// round 3
// baseline (speedup 1.0000x reference)
#include <cuda_runtime.h>
#include <math_constants.h>

// Problem constants (pinned by the dataset)
#define BATCH   32
#define HEADS   32
#define HKV     8
#define GQA     4      // HEADS / HKV
#define DIM     128    // head dim, == Lv
#define S_MAX   8      // max kv splits
#define NWARP   4
#define NTHREAD 128

__global__ __launch_bounds__(NTHREAD, 8)
void decode_attn_stage1(const float* __restrict__ q,
                        const float* __restrict__ k_buf,
                        const float* __restrict__ v_buf,
                        const int*   __restrict__ kv_indptr,
                        const int*   __restrict__ kv_indices,
                        const int*   __restrict__ num_kv_splits,
                        float* __restrict__ att_out,   // [B, H, S, DIM]
                        float* __restrict__ att_lse)   // [B, H, S]
{
    const int bid  = blockIdx.x;
    const int s    = bid % S_MAX;
    const int hkv  = (bid / S_MAX) % HKV;
    const int b    = bid / (S_MAX * HKV);

    const int tid  = threadIdx.x;
    const int lane = tid & 31;
    const int w    = tid >> 5;

    const int p0      = kv_indptr[b];
    const int seq_len = kv_indptr[b + 1] - p0;
    const int nsp     = num_kv_splits[b];
    // kv_len_per_split = cdiv(cdiv(seq_len, nsp), 32) * 32
    const int klps = (((seq_len + nsp - 1) / nsp) + 31) / 32 * 32;
    const int t0 = s * klps;
    const int t1 = min(t0 + klps, seq_len);

    // Load q fragments (pre-scaled by sm_scale)
    const float sm_scale = 0.08838834764831845f;  // 1/sqrt(128)
    float4 q4[GQA];
#pragma unroll
    for (int g = 0; g < GQA; g++) {
        const float4* qp = reinterpret_cast<const float4*>(
            q + ((size_t)b * HEADS + hkv * GQA + g) * DIM);
        float4 t = qp[lane];
        q4[g] = make_float4(t.x * sm_scale, t.y * sm_scale,
                            t.z * sm_scale, t.w * sm_scale);
    }

    float  m[GQA], l[GQA];
    float4 acc[GQA];
#pragma unroll
    for (int g = 0; g < GQA; g++) {
        m[g] = -CUDART_INF_F;
        l[g] = 0.0f;
        acc[g] = make_float4(0.f, 0.f, 0.f, 0.f);
    }

    // Main loop: one warp per token, strided by NWARP
    for (int t = t0 + w; t < t1; t += NWARP) {
        const int loc = __ldg(kv_indices + p0 + t);
        const size_t row = ((size_t)loc * HKV + hkv) * DIM;
        const float4 k4 = reinterpret_cast<const float4*>(k_buf + row)[lane];
        const float4 v4 = reinterpret_cast<const float4*>(v_buf + row)[lane];

        float d[GQA];
#pragma unroll
        for (int g = 0; g < GQA; g++) {
            d[g] = q4[g].x * k4.x;
            d[g] = fmaf(q4[g].y, k4.y, d[g]);
            d[g] = fmaf(q4[g].z, k4.z, d[g]);
            d[g] = fmaf(q4[g].w, k4.w, d[g]);
        }
#pragma unroll
        for (int off = 16; off > 0; off >>= 1) {
#pragma unroll
            for (int g = 0; g < GQA; g++)
                d[g] += __shfl_xor_sync(0xFFFFFFFFu, d[g], off);
        }
#pragma unroll
        for (int g = 0; g < GQA; g++) {
            const float mn = fmaxf(m[g], d[g]);
            const float sc = __expf(m[g] - mn);   // exp(-inf)=0 on first token
            const float p  = __expf(d[g] - mn);
            l[g] = l[g] * sc + p;
            acc[g].x = fmaf(p, v4.x, acc[g].x * sc);
            acc[g].y = fmaf(p, v4.y, acc[g].y * sc);
            acc[g].z = fmaf(p, v4.z, acc[g].z * sc);
            acc[g].w = fmaf(p, v4.w, acc[g].w * sc);
            m[g] = mn;
        }
    }

    // Cross-warp combine via shared memory
    __shared__ float  sm_m[NWARP][GQA];
    __shared__ float  sm_l[NWARP][GQA];
    __shared__ float4 sm_acc[NWARP][GQA][32];

    if (lane == 0) {
#pragma unroll
        for (int g = 0; g < GQA; g++) {
            sm_m[w][g] = m[g];
            sm_l[w][g] = l[g];
        }
    }
#pragma unroll
    for (int g = 0; g < GQA; g++)
        sm_acc[w][g][lane] = acc[g];
    __syncthreads();

    // Warp g finalizes head g
    const int g = w;
    float mf = -CUDART_INF_F;
#pragma unroll
    for (int ww = 0; ww < NWARP; ww++)
        mf = fmaxf(mf, sm_m[ww][g]);

    float  lf = 0.0f;
    float4 af = make_float4(0.f, 0.f, 0.f, 0.f);
#pragma unroll
    for (int ww = 0; ww < NWARP; ww++) {
        const float mw = sm_m[ww][g];
        const float sc = (mw == -CUDART_INF_F) ? 0.0f : __expf(mw - mf);
        lf += sm_l[ww][g] * sc;
        const float4 a = sm_acc[ww][g][lane];
        af.x = fmaf(a.x, sc, af.x);
        af.y = fmaf(a.y, sc, af.y);
        af.z = fmaf(a.z, sc, af.z);
        af.w = fmaf(a.w, sc, af.w);
    }

    const float inv = (lf > 0.0f) ? (1.0f / lf) : 0.0f;
    const int   h   = hkv * GQA + g;
    const size_t ob = (((size_t)b * HEADS + h) * S_MAX + s) * DIM;
    float4 o = make_float4(af.x * inv, af.y * inv, af.z * inv, af.w * inv);
    reinterpret_cast<float4*>(att_out + ob)[lane] = o;
    if (lane == 0)
        att_lse[((size_t)b * HEADS + h) * S_MAX + s] = mf + logf(lf);
}

extern "C" void kernel_launch(void* const* d_in, const int* in_sizes, int n_in,
                              void* d_out, int out_size) {
    const float* q          = (const float*)d_in[0];
    const float* k_buffer   = (const float*)d_in[1];
    const float* v_buffer   = (const float*)d_in[2];
    const int*   kv_indptr  = (const int*)d_in[3];
    const int*   kv_indices = (const int*)d_in[4];
    const int*   nks        = (const int*)d_in[5];

    float* att_out = (float*)d_out;                                  // B*H*S*DIM
    float* att_lse = att_out + (size_t)BATCH * HEADS * S_MAX * DIM;  // B*H*S

    dim3 grid(BATCH * HKV * S_MAX);
    dim3 block(NTHREAD);
    decode_attn_stage1<<<grid, block>>>(q, k_buffer, v_buffer,
                                        kv_indptr, kv_indices, nks,
                                        att_out, att_lse);
}